// round 13
// baseline (speedup 1.0000x reference)
#include <cuda_runtime.h>
#include <cuda_bf16.h>

// YOLO layer: x [B=16, C=255, 64, 64] fp32, anchors [3,2] fp32.
// pred = x.reshape(B, 3, 85, 64, 64).transpose(0,1,3,4,2)
// Outputs concatenated in d_out (float32):
//   boxes [B,3,64,64,4]  : 786,432    elems at offset 0
//   conf  [B,3,64,64]    : 196,608    elems at offset 786,432
//   cls   [B,3,64,64,80] : 15,728,640 elems at offset 983,040
//
// R12: R11 retry with legal stores. sm_103a ptxas requires 256-bit
// stores for L2::evict_last -> all output stores are now
// st.global.L2::evict_last.v8.b32 (32B, sector-exact). Theory
// unchanged: make the 66.8MB output the L2-resident set so graph
// replays overwrite dirty lines in place and DRAM sees mostly the
// input read stream (prior rounds: ~87MB real DRAM traffic/iter,
// write-dominated, all-pipes-at-50% plateau at ~21us).
//   cls: 80 elems/pos divisible by 8 -> each 32B chunk is within one
//        position: p=f/10, channels 5+8*(f%10).. Warp store = 1KB
//        contiguous.
//   boxes: 2 positions (32B) per thread, lanes 0..31 -> 1KB contiguous.
//   conf: 8 floats per thread, threads 32..39.
// sigmoid via MUFU.TANH: sig(x) = fma(0.5, tanh(0.5x), 0.5).

#define NT 256
#define TP 64
#define PITCH 65            // floats per smem channel row; bank = (c + p) % 32

__device__ __forceinline__ float sigf(float v) {
    float t;
    asm("tanh.approx.f32 %0, %1;" : "=f"(t) : "f"(v * 0.5f));
    return fmaf(0.5f, t, 0.5f);
}

__device__ __forceinline__ void st_el_f8(float* p, const float* v) {
    asm volatile(
        "st.global.L2::evict_last.v8.b32 [%0], {%1,%2,%3,%4,%5,%6,%7,%8};"
        :: "l"(p),
           "r"(__float_as_uint(v[0])), "r"(__float_as_uint(v[1])),
           "r"(__float_as_uint(v[2])), "r"(__float_as_uint(v[3])),
           "r"(__float_as_uint(v[4])), "r"(__float_as_uint(v[5])),
           "r"(__float_as_uint(v[6])), "r"(__float_as_uint(v[7]))
        : "memory");
}

__global__ __launch_bounds__(NT) void yolo_kernel(
    const float* __restrict__ x,
    const float* __restrict__ anchors,
    float* __restrict__ out)
{
    constexpr int A    = 3;
    constexpr int CH   = 85;
    constexpr int P    = 64 * 64;                     // 4096 positions per (b,a)
    constexpr int Btot = 16;
    constexpr int CONF_OFF = Btot * A * P * 4;        // 786432
    constexpr int CLS_OFF  = CONF_OFF + Btot * A * P; // 983040

    __shared__ float tile[CH * PITCH];                // 85 x 65 = 22.1 KB

    const int blk = blockIdx.x;
    const int ba  = blk >> 6;                         // 64 tiles per (b,a)
    const int p0  = (blk & 63) * TP;
    const int t   = threadIdx.x;

    // ---- Load: 85 ch x 16 float4, input-coalesced, default L2 policy ----
    const float4* xin4 = reinterpret_cast<const float4*>(
        x + (size_t)ba * CH * P + p0);                // p0 multiple of 64 -> aligned
    #pragma unroll
    for (int k = 0; k < 6; k++) {
        const int idx = t + k * NT;                   // 0..1535, need < 1360
        if (idx < CH * (TP / 4)) {
            const int c = idx >> 4;                   // channel
            const int q = idx & 15;
            float4 v = xin4[c * (P / 4) + q];
            const int base = c * PITCH + 4 * q;
            tile[base + 0] = v.x;
            tile[base + 1] = v.y;
            tile[base + 2] = v.z;
            tile[base + 3] = v.w;
        }
    }
    __syncthreads();

    // ---- cls: 640 x 32B chunks, output-linear; warp store = 1KB contig ----
    {
        float* ocls = out + CLS_OFF + (size_t)(ba * P + p0) * 80;
        #pragma unroll
        for (int k = 0; k < 3; k++) {
            const int f = t + k * NT;                 // chunk id, need < 640
            if (k < 2 || f < 640) {
                const int p  = f / 10;                // position in tile (0..63)
                const int j8 = f - 10 * p;            // 32B chunk in position (0..9)
                const int c  = 5 + 8 * j8;            // channels c..c+7
                float o[8];
                #pragma unroll
                for (int i = 0; i < 8; i++)
                    o[i] = sigf(tile[(c + i) * PITCH + p]);
                st_el_f8(ocls + (size_t)f * 8, o);
            }
        }
    }

    // ---- boxes: lanes 0..31, 2 positions (32B) each; warp = 1KB contig ----
    if (t < 32) {
        const int a  = ba - (ba / A) * A;
        const float aw = __ldg(anchors + a * 2 + 0);
        const float ah = __ldg(anchors + a * 2 + 1);
        float o[8];
        #pragma unroll
        for (int h = 0; h < 2; h++) {
            const int p  = 2 * t + h;
            const int pg = p0 + p;
            o[4*h + 0] = (sigf(tile[0 * PITCH + p]) + (float)(pg >> 6)) * (1.0f / 64.0f);
            o[4*h + 1] = (sigf(tile[1 * PITCH + p]) + (float)(pg & 63)) * (1.0f / 64.0f);
            o[4*h + 2] = __expf(tile[2 * PITCH + p]) * aw;
            o[4*h + 3] = __expf(tile[3 * PITCH + p]) * ah;
        }
        st_el_f8(out + (size_t)(ba * P + p0 + 2 * t) * 4, o);
    }
    // ---- conf: threads 32..39, 8 floats each; 256B contiguous ----
    else if (t < 40) {
        const int q = t - 32;                         // 0..7
        float o[8];
        #pragma unroll
        for (int i = 0; i < 8; i++)
            o[i] = sigf(tile[4 * PITCH + 8 * q + i]);
        st_el_f8(out + CONF_OFF + ba * P + p0 + 8 * q, o);
    }
}

extern "C" void kernel_launch(void* const* d_in, const int* in_sizes, int n_in,
                              void* d_out, int out_size) {
    const float* x       = (const float*)d_in[0];
    const float* anchors = (const float*)d_in[1];
    float*       out     = (float*)d_out;
    yolo_kernel<<<3072, NT>>>(x, anchors, out);
}